// round 13
// baseline (speedup 1.0000x reference)
#include <cuda_runtime.h>
#include <cuda_fp16.h>
#include <math_constants.h>

#define IMG_H 1024
#define IMG_W 1024
#define IMG   (IMG_H * IMG_W)
#define NIMG  16
#define NF    32            // [0..15]=pred(sigmoid(logits)), [16..31]=gt(target)
#define OUTC  240           // emitted cols per warp (256-col window, lanes 0/31 halo)
#define XT    5             // ceil(1024/240)
#define R     32            // emitted rows per warp
#define NWARP 4

__device__ __half  g_bufA[(size_t)NF * IMG];   // 64 MB scratch
__device__ double  g_acc[NF];                  // [0..15]=tp, [16..31]=ts

struct __align__(16) h8 { __half2 a, b, c, d; };   // 8 cols per lane (4 regs)

__device__ __forceinline__ float sigmoidf(float x) { return 1.f / (1.f + __expf(-x)); }
__device__ __forceinline__ unsigned h2u(__half2 v) { return *(unsigned*)&v; }
__device__ __forceinline__ __half2  u2h(unsigned u) { return *(__half2*)&u; }
__device__ __forceinline__ __half2 pmh(__half2 x, __half2 y) {   // (hi x, lo y)
    return u2h(__byte_perm(h2u(x), h2u(y), 0x5432));
}
__device__ __forceinline__ h8 vmin38(h8 x, h8 y, h8 z) {
    h8 o;
    o.a = __hmin2(x.a, __hmin2(y.a, z.a));
    o.b = __hmin2(x.b, __hmin2(y.b, z.b));
    o.c = __hmin2(x.c, __hmin2(y.c, z.c));
    o.d = __hmin2(x.d, __hmin2(y.d, z.d));
    return o;
}
__device__ __forceinline__ h8 vmax38(h8 x, h8 y, h8 z) {
    h8 o;
    o.a = __hmax2(x.a, __hmax2(y.a, z.a));
    o.b = __hmax2(x.b, __hmax2(y.b, z.b));
    o.c = __hmax2(x.c, __hmax2(y.c, z.c));
    o.d = __hmax2(x.d, __hmax2(y.d, z.d));
    return o;
}
__device__ __forceinline__ h8 hmin8(h8 v) {
    __half2 L  = u2h(__shfl_up_sync(0xffffffffu, h2u(v.d), 1));
    __half2 Rt = u2h(__shfl_down_sync(0xffffffffu, h2u(v.a), 1));
    __half2 p0 = pmh(L,   v.a), p1 = pmh(v.a, v.b), p2 = pmh(v.b, v.c);
    __half2 p3 = pmh(v.c, v.d), p4 = pmh(v.d, Rt);
    h8 o;
    o.a = __hmin2(p0, __hmin2(v.a, p1));
    o.b = __hmin2(p1, __hmin2(v.b, p2));
    o.c = __hmin2(p2, __hmin2(v.c, p3));
    o.d = __hmin2(p3, __hmin2(v.d, p4));
    return o;
}
__device__ __forceinline__ h8 hmax8(h8 v) {
    __half2 L  = u2h(__shfl_up_sync(0xffffffffu, h2u(v.d), 1));
    __half2 Rt = u2h(__shfl_down_sync(0xffffffffu, h2u(v.a), 1));
    __half2 p0 = pmh(L,   v.a), p1 = pmh(v.a, v.b), p2 = pmh(v.b, v.c);
    __half2 p3 = pmh(v.c, v.d), p4 = pmh(v.d, Rt);
    h8 o;
    o.a = __hmax2(p0, __hmax2(v.a, p1));
    o.b = __hmax2(p1, __hmax2(v.b, p2));
    o.c = __hmax2(p2, __hmax2(v.c, p3));
    o.d = __hmax2(p3, __hmax2(v.d, p4));
    return o;
}
__device__ __forceinline__ h8 upd8(h8 x, h8 op, h8 er) {   // clamp01(x-(op-er))
    const __half2 Z = __float2half2_rn(0.f), O = __float2half2_rn(1.f);
    h8 o;
    o.a = __hmin2(__hmax2(__hsub2(x.a, __hsub2(op.a, er.a)), Z), O);
    o.b = __hmin2(__hmax2(__hsub2(x.b, __hsub2(op.b, er.b)), Z), O);
    o.c = __hmin2(__hmax2(__hsub2(x.c, __hsub2(op.c, er.c)), Z), O);
    o.d = __hmin2(__hmax2(__hsub2(x.d, __hsub2(op.d, er.d)), Z), O);
    return o;
}
__device__ __forceinline__ h8 maskN8(h8 e, __half2 m) {   // invalid lane -> -inf
    h8 o; o.a = __hmin2(e.a, m); o.b = __hmin2(e.b, m);
    o.c = __hmin2(e.c, m); o.d = __hmin2(e.d, m); return o;
}
__device__ __forceinline__ h8 maskP8(h8 e, __half2 m) {   // invalid lane -> +inf
    h8 o; o.a = __hmax2(e.a, m); o.b = __hmax2(e.b, m);
    o.c = __hmax2(e.c, m); o.d = __hmax2(e.d, m); return o;
}

// ---------------------------------------------------------------------------
// Pass A: x = sigmoid(logits) | (float)target; 2 skeleton iterations (lag 4);
//         store half. One-row load prefetch (xn) hides LDG latency.
// ---------------------------------------------------------------------------
__global__ void __launch_bounds__(NWARP * 32)
skelA_kernel(const float* __restrict__ logits, const int* __restrict__ target,
             __half* __restrict__ dst)
{
    const int lane = threadIdx.x & 31;
    const int z    = blockIdx.z;
    const int c0   = blockIdx.x * OUTC - 8 + lane * 8;
    const int row0 = (blockIdx.y * NWARP + (threadIdx.x >> 5)) * R;
    const bool colsOK = (c0 >= 0) && (c0 < IMG_W);

    if (blockIdx.x == 0 && blockIdx.y == 0 && blockIdx.z == 0 && threadIdx.x < NF)
        g_acc[threadIdx.x] = 0.0;

    const int img = (z < NIMG) ? z : z - NIMG;
    const float* __restrict__ lg = logits + (size_t)img * IMG;
    const int*   __restrict__ tg = target + (size_t)img * IMG;
    __half* __restrict__ dp = dst + (size_t)z * IMG;

    const __half2 INF2  = __half2half2(__ushort_as_half(0x7C00));
    const __half2 NINF2 = __half2half2(__ushort_as_half(0xFC00));
    h8 P8; P8.a = INF2;  P8.b = INF2;  P8.c = INF2;  P8.d = INF2;
    h8 N8; N8.a = NINF2; N8.b = NINF2; N8.c = NINF2; N8.d = NINF2;
    const __half2 mN2 = colsOK ? INF2 : NINF2;
    const __half2 mP2 = colsOK ? NINF2 : INF2;
    const bool emitLane = (lane >= 1) && (lane <= 30) && colsOK;

    auto ldF = [&](int r) -> h8 {
        size_t off = (size_t)r * IMG_W + c0;
        h8 o;
        if (z < NIMG) {
            float4 f1 = __ldg((const float4*)(lg + off));
            float4 f2 = __ldg((const float4*)(lg + off + 4));
            o.a = __floats2half2_rn(sigmoidf(f1.x), sigmoidf(f1.y));
            o.b = __floats2half2_rn(sigmoidf(f1.z), sigmoidf(f1.w));
            o.c = __floats2half2_rn(sigmoidf(f2.x), sigmoidf(f2.y));
            o.d = __floats2half2_rn(sigmoidf(f2.z), sigmoidf(f2.w));
        } else {
            int4 t1 = __ldg((const int4*)(tg + off));
            int4 t2 = __ldg((const int4*)(tg + off + 4));
            o.a = __floats2half2_rn((float)t1.x, (float)t1.y);
            o.b = __floats2half2_rn((float)t1.z, (float)t1.w);
            o.c = __floats2half2_rn((float)t2.x, (float)t2.y);
            o.d = __floats2half2_rn((float)t2.z, (float)t2.w);
        }
        return o;
    };
    auto ldrow = [&](int r) -> h8 {
        if (!colsOK || (unsigned)r >= IMG_H) return P8;
        return ldF(r);
    };
    auto store8 = [&](int r, h8 v) {
        uint4 u; u.x = h2u(v.a); u.y = h2u(v.b); u.z = h2u(v.c); u.w = h2u(v.d);
        *(uint4*)(dp + (size_t)r * IMG_W + c0) = u;
    };

    const bool cint = (blockIdx.x > 0) && (blockIdx.x < gridDim.x - 1);
    const bool rint = (row0 >= 4) && (row0 + R + 5 <= IMG_H);   // +1 for prefetch

    h8 xa, xb, xn, e1a = N8, e1b = N8, pa = P8, pb = P8, qa = N8, qb = N8;

    if (cint && rint) {
        xa = ldF(row0 - 4); xb = ldF(row0 - 3); xn = ldF(row0 - 2);
        #pragma unroll 2
        for (int k = row0 - 3; k <= row0 + R + 2; ++k) {
            h8 xc = xn;                 // row k+1 (already in flight)
            xn = ldF(k + 2);            // prefetch row k+2 (max row0+R+4 < IMG_H)
            h8 e1 = hmin8(vmin38(xa, xb, xc));                      // row k
            h8 xp = upd8(xa, hmax8(vmax38(e1a, e1b, e1)), e1b);     // row k-1
            h8 e2 = hmin8(vmin38(pa, pb, xp));                      // row k-2
            if (k >= row0 + 3) {
                h8 nx = upd8(pa, hmax8(vmax38(qa, qb, e2)), qb);    // row k-3
                if (emitLane) store8(k - 3, nx);
            }
            qa = qb; qb = e2; pa = pb; pb = xp;
            e1a = e1b; e1b = e1; xa = xb; xb = xc;
        }
    } else {
        xa = ldrow(row0 - 4); xb = ldrow(row0 - 3); xn = ldrow(row0 - 2);
        for (int k = row0 - 3; k <= row0 + R + 2; ++k) {
            h8 xc = xn;
            xn = ldrow(k + 2);
            h8 e1 = ((unsigned)k < IMG_H)
                  ? maskN8(hmin8(vmin38(xa, xb, xc)), mN2) : N8;
            h8 xp = ((unsigned)(k - 1) < IMG_H)
                  ? maskP8(upd8(xa, hmax8(vmax38(e1a, e1b, e1)), e1b), mP2) : P8;
            h8 e2 = ((unsigned)(k - 2) < IMG_H)
                  ? maskN8(hmin8(vmin38(pa, pb, xp)), mN2) : N8;
            if (k >= row0 + 3) {
                h8 nx = upd8(pa, hmax8(vmax38(qa, qb, e2)), qb);
                if (emitLane) store8(k - 3, nx);
            }
            qa = qb; qb = e2; pa = pb; pb = xp;
            e1a = e1b; e1b = e1; xa = xb; xb = xc;
        }
    }
}

// ---------------------------------------------------------------------------
// Pass B: load half buffer; 3 skeleton iterations (lag 6); accumulate tp/ts.
// One-row load prefetch on the skeleton input stream.
// ---------------------------------------------------------------------------
__global__ void __launch_bounds__(NWARP * 32)
skelB_kernel(const __half* __restrict__ src,
             const float* __restrict__ logits, const int* __restrict__ target)
{
    const int lane = threadIdx.x & 31;
    const int warp = threadIdx.x >> 5;
    const int z    = blockIdx.z;
    const int c0   = blockIdx.x * OUTC - 8 + lane * 8;
    const int row0 = (blockIdx.y * NWARP + warp) * R;
    const bool colsOK = (c0 >= 0) && (c0 < IMG_W);

    const int img = (z < NIMG) ? z : z - NIMG;
    const float* __restrict__ lg = logits + (size_t)img * IMG;
    const int*   __restrict__ tg = target + (size_t)img * IMG;
    const __half* __restrict__ sp = src + (size_t)z * IMG;

    const __half2 INF2  = __half2half2(__ushort_as_half(0x7C00));
    const __half2 NINF2 = __half2half2(__ushort_as_half(0xFC00));
    h8 P8; P8.a = INF2;  P8.b = INF2;  P8.c = INF2;  P8.d = INF2;
    h8 N8; N8.a = NINF2; N8.b = NINF2; N8.c = NINF2; N8.d = NINF2;
    const __half2 mN2 = colsOK ? INF2 : NINF2;
    const __half2 mP2 = colsOK ? NINF2 : INF2;
    const bool emitLane = (lane >= 1) && (lane <= 30) && colsOK;

    auto ldF = [&](int r) -> h8 {
        uint4 u = __ldg((const uint4*)(sp + (size_t)r * IMG_W + c0));
        h8 o; o.a = u2h(u.x); o.b = u2h(u.y); o.c = u2h(u.z); o.d = u2h(u.w);
        return o;
    };
    auto ldrow = [&](int r) -> h8 {
        if (!colsOK || (unsigned)r >= IMG_H) return P8;
        return ldF(r);
    };

    float accum = 0.f;
    auto accum8 = [&](int r, h8 nx) {
        size_t ob = (size_t)r * IMG_W + c0;
        float w[8];
        if (z < NIMG) {
            int4 t1 = __ldg((const int4*)(tg + ob));
            int4 t2 = __ldg((const int4*)(tg + ob + 4));
            w[0]=(float)t1.x; w[1]=(float)t1.y; w[2]=(float)t1.z; w[3]=(float)t1.w;
            w[4]=(float)t2.x; w[5]=(float)t2.y; w[6]=(float)t2.z; w[7]=(float)t2.w;
        } else {
            float4 f1 = __ldg((const float4*)(lg + ob));
            float4 f2 = __ldg((const float4*)(lg + ob + 4));
            w[0]=sigmoidf(f1.x); w[1]=sigmoidf(f1.y); w[2]=sigmoidf(f1.z); w[3]=sigmoidf(f1.w);
            w[4]=sigmoidf(f2.x); w[5]=sigmoidf(f2.y); w[6]=sigmoidf(f2.z); w[7]=sigmoidf(f2.w);
        }
        float2 f0 = __half22float2(nx.a), f1 = __half22float2(nx.b);
        float2 f2 = __half22float2(nx.c), f3 = __half22float2(nx.d);
        accum += f0.x * w[0] + f0.y * w[1] + f1.x * w[2] + f1.y * w[3]
               + f2.x * w[4] + f2.y * w[5] + f3.x * w[6] + f3.y * w[7];
    };

    const bool cint = (blockIdx.x > 0) && (blockIdx.x < gridDim.x - 1);
    const bool rint = (row0 >= 6) && (row0 + R + 7 <= IMG_H);   // +1 for prefetch

    // 3-stage rolling pipeline (lag 6), state 12 x h8 + prefetch
    h8 xa, xb, xn, e1a = N8, e1b = N8, pa = P8, pb = P8,
       e2a = N8, e2b = N8, ra = P8, rb = P8, e3a = N8, e3b = N8;

    if (cint && rint) {
        xa = ldF(row0 - 6); xb = ldF(row0 - 5); xn = ldF(row0 - 4);
        #pragma unroll 2
        for (int k = row0 - 5; k <= row0 + R + 4; ++k) {
            h8 xc = xn;                 // row k+1
            xn = ldF(k + 2);            // prefetch row k+2 (max row0+R+6 < IMG_H)
            h8 e1 = hmin8(vmin38(xa, xb, xc));                        // row k
            h8 xp = upd8(xa, hmax8(vmax38(e1a, e1b, e1)), e1b);       // row k-1
            h8 e2 = hmin8(vmin38(pa, pb, xp));                        // row k-2
            h8 xq = upd8(pa, hmax8(vmax38(e2a, e2b, e2)), e2b);       // row k-3
            h8 e3 = hmin8(vmin38(ra, rb, xq));                        // row k-4
            if (k >= row0 + 5) {
                h8 nx = upd8(ra, hmax8(vmax38(e3a, e3b, e3)), e3b);   // row k-5
                if (emitLane) accum8(k - 5, nx);
            }
            e3a = e3b; e3b = e3; ra = rb; rb = xq;
            e2a = e2b; e2b = e2; pa = pb; pb = xp;
            e1a = e1b; e1b = e1; xa = xb; xb = xc;
        }
    } else {
        xa = ldrow(row0 - 6); xb = ldrow(row0 - 5); xn = ldrow(row0 - 4);
        for (int k = row0 - 5; k <= row0 + R + 4; ++k) {
            h8 xc = xn;
            xn = ldrow(k + 2);
            h8 e1 = ((unsigned)k < IMG_H)
                  ? maskN8(hmin8(vmin38(xa, xb, xc)), mN2) : N8;
            h8 xp = ((unsigned)(k - 1) < IMG_H)
                  ? maskP8(upd8(xa, hmax8(vmax38(e1a, e1b, e1)), e1b), mP2) : P8;
            h8 e2 = ((unsigned)(k - 2) < IMG_H)
                  ? maskN8(hmin8(vmin38(pa, pb, xp)), mN2) : N8;
            h8 xq = ((unsigned)(k - 3) < IMG_H)
                  ? maskP8(upd8(pa, hmax8(vmax38(e2a, e2b, e2)), e2b), mP2) : P8;
            h8 e3 = ((unsigned)(k - 4) < IMG_H)
                  ? maskN8(hmin8(vmin38(ra, rb, xq)), mN2) : N8;
            if (k >= row0 + 5) {
                h8 nx = upd8(ra, hmax8(vmax38(e3a, e3b, e3)), e3b);
                if (emitLane) accum8(k - 5, nx);
            }
            e3a = e3b; e3b = e3; ra = rb; rb = xq;
            e2a = e2b; e2b = e2; pa = pb; pb = xp;
            e1a = e1b; e1b = e1; xa = xb; xb = xc;
        }
    }

    #pragma unroll
    for (int o = 16; o > 0; o >>= 1)
        accum += __shfl_down_sync(0xffffffffu, accum, o);
    __shared__ float sacc[NWARP];
    if (lane == 0) sacc[warp] = accum;
    __syncthreads();
    if (threadIdx.x == 0) {
        float t = 0.f;
        #pragma unroll
        for (int i = 0; i < NWARP; ++i) t += sacc[i];
        atomicAdd(&g_acc[z], (double)t);
    }
}

// ---------------------------------------------------------------------------
__global__ void final_kernel(float* __restrict__ out)
{
    const int t = threadIdx.x;
    float v = 0.f;
    if (t < NIMG) {
        double tp = g_acc[t], ts = g_acc[NIMG + t];
        double num = 2.0 * tp * ts;
        double den = tp + ts;
        double c = (den > 0.0) ? (num + 1e-6) / (den + 1e-6) : 1.0;
        c = fmin(fmax(c, 0.0), 1.0);
        v = (float)(1.0 - c);
    }
    for (int o = 16; o > 0; o >>= 1) v += __shfl_down_sync(0xffffffffu, v, o);
    if (t == 0) out[0] = v / (float)NIMG;
}

// ---------------------------------------------------------------------------
extern "C" void kernel_launch(void* const* d_in, const int* in_sizes, int n_in,
                              void* d_out, int out_size)
{
    const float* logits = (const float*)d_in[0];
    const int*   target = (const int*)d_in[1];
    float*       out    = (float*)d_out;

    __half* A = nullptr;
    cudaGetSymbolAddress((void**)&A, g_bufA);

    dim3 grid(XT, IMG_H / (R * NWARP), NF);   // 5 x 8 x 32 = 1280 blocks
    const int blk = NWARP * 32;

    skelA_kernel<<<grid, blk>>>(logits, target, A);   // sigmoid + iters 1-2
    skelB_kernel<<<grid, blk>>>(A, logits, target);   // iters 3-5 + reduce
    final_kernel<<<1, 32>>>(out);
}

// round 16
// speedup vs baseline: 1.3042x; 1.3042x over previous
#include <cuda_runtime.h>
#include <cuda_fp16.h>
#include <math_constants.h>

#define IMG_H 1024
#define IMG_W 1024
#define IMG   (IMG_H * IMG_W)
#define NIMG  16
#define NF    32            // [0..15]=pred(sigmoid(logits)), [16..31]=gt(target)
#define OUTC  240           // emitted cols per warp (256-col window, lanes 0/31 halo)
#define XT    5             // ceil(1024/240)
#define R     32            // emitted rows per warp
#define NWARP 4

__device__ __half  g_bufA[(size_t)NF * IMG];   // 64 MB scratch
__device__ __half  g_bufB[(size_t)NF * IMG];   // 64 MB scratch
__device__ double  g_acc[NF];                  // [0..15]=tp, [16..31]=ts

struct __align__(16) h8 { __half2 a, b, c, d; };   // 8 cols per lane

// sigmoid via MUFU.TANH: 1 MUFU + 2 FMA (vs 2 MUFU for expf+rcp)
__device__ __forceinline__ float sigmoidf(float x) {
    float t;
    asm("tanh.approx.f32 %0, %1;" : "=f"(t) : "f"(0.5f * x));
    return fmaf(0.5f, t, 0.5f);
}
__device__ __forceinline__ unsigned h2u(__half2 v) { return *(unsigned*)&v; }
__device__ __forceinline__ __half2  u2h(unsigned u) { return *(__half2*)&u; }
__device__ __forceinline__ __half2 pmh(__half2 x, __half2 y) {   // (hi x, lo y)
    return u2h(__byte_perm(h2u(x), h2u(y), 0x5432));
}
__device__ __forceinline__ h8 vmin38(h8 x, h8 y, h8 z) {
    h8 o;
    o.a = __hmin2(x.a, __hmin2(y.a, z.a));
    o.b = __hmin2(x.b, __hmin2(y.b, z.b));
    o.c = __hmin2(x.c, __hmin2(y.c, z.c));
    o.d = __hmin2(x.d, __hmin2(y.d, z.d));
    return o;
}
__device__ __forceinline__ h8 vmax38(h8 x, h8 y, h8 z) {
    h8 o;
    o.a = __hmax2(x.a, __hmax2(y.a, z.a));
    o.b = __hmax2(x.b, __hmax2(y.b, z.b));
    o.c = __hmax2(x.c, __hmax2(y.c, z.c));
    o.d = __hmax2(x.d, __hmax2(y.d, z.d));
    return o;
}
__device__ __forceinline__ h8 hmin8(h8 v) {
    __half2 L  = u2h(__shfl_up_sync(0xffffffffu, h2u(v.d), 1));
    __half2 Rt = u2h(__shfl_down_sync(0xffffffffu, h2u(v.a), 1));
    __half2 p0 = pmh(L,   v.a), p1 = pmh(v.a, v.b), p2 = pmh(v.b, v.c);
    __half2 p3 = pmh(v.c, v.d), p4 = pmh(v.d, Rt);
    h8 o;
    o.a = __hmin2(p0, __hmin2(v.a, p1));
    o.b = __hmin2(p1, __hmin2(v.b, p2));
    o.c = __hmin2(p2, __hmin2(v.c, p3));
    o.d = __hmin2(p3, __hmin2(v.d, p4));
    return o;
}
__device__ __forceinline__ h8 hmax8(h8 v) {
    __half2 L  = u2h(__shfl_up_sync(0xffffffffu, h2u(v.d), 1));
    __half2 Rt = u2h(__shfl_down_sync(0xffffffffu, h2u(v.a), 1));
    __half2 p0 = pmh(L,   v.a), p1 = pmh(v.a, v.b), p2 = pmh(v.b, v.c);
    __half2 p3 = pmh(v.c, v.d), p4 = pmh(v.d, Rt);
    h8 o;
    o.a = __hmax2(p0, __hmax2(v.a, p1));
    o.b = __hmax2(p1, __hmax2(v.b, p2));
    o.c = __hmax2(p2, __hmax2(v.c, p3));
    o.d = __hmax2(p3, __hmax2(v.d, p4));
    return o;
}
__device__ __forceinline__ h8 upd8(h8 x, h8 op, h8 er) {   // clamp01(x-(op-er))
    const __half2 Z = __float2half2_rn(0.f), O = __float2half2_rn(1.f);
    h8 o;
    o.a = __hmin2(__hmax2(__hsub2(x.a, __hsub2(op.a, er.a)), Z), O);
    o.b = __hmin2(__hmax2(__hsub2(x.b, __hsub2(op.b, er.b)), Z), O);
    o.c = __hmin2(__hmax2(__hsub2(x.c, __hsub2(op.c, er.c)), Z), O);
    o.d = __hmin2(__hmax2(__hsub2(x.d, __hsub2(op.d, er.d)), Z), O);
    return o;
}
__device__ __forceinline__ h8 maskN8(h8 e, __half2 m) {   // invalid lane -> -inf
    h8 o; o.a = __hmin2(e.a, m); o.b = __hmin2(e.b, m);
    o.c = __hmin2(e.c, m); o.d = __hmin2(e.d, m); return o;
}
__device__ __forceinline__ h8 maskP8(h8 e, __half2 m) {   // invalid lane -> +inf
    h8 o; o.a = __hmax2(e.a, m); o.b = __hmax2(e.b, m);
    o.c = __hmax2(e.c, m); o.d = __hmax2(e.d, m); return o;
}

// ---------------------------------------------------------------------------
// MODE 0: x = sigmoid(logits)/(float)target; 2 skeleton iterations; store half.
// MODE 1: load half buffer; 2 skeleton iterations; store half.
// MODE 2: load half buffer; 1 skeleton iteration; accumulate tp/ts.
// Lane owns 8 cols (4x half2, one uint4 per row). Window 256 cols, emit 240.
// ---------------------------------------------------------------------------
template<int MODE>
__global__ void __launch_bounds__(NWARP * 32)
skel_kernel(const __half* __restrict__ src,
            const float*  __restrict__ logits,
            const int*    __restrict__ target,
            __half*       __restrict__ dst)
{
    const int lane = threadIdx.x & 31;
    const int warp = threadIdx.x >> 5;
    const int z    = blockIdx.z;
    const int c0   = blockIdx.x * OUTC - 8 + lane * 8;   // multiple of 8
    const int row0 = (blockIdx.y * NWARP + warp) * R;
    const bool colsOK = (c0 >= 0) && (c0 < IMG_W);       // whole-lane validity

    if (MODE == 0 && blockIdx.x == 0 && blockIdx.y == 0 && blockIdx.z == 0 &&
        threadIdx.x < NF)
        g_acc[threadIdx.x] = 0.0;   // stream-ordered before MODE 2 atomics

    const int img = (z < NIMG) ? z : z - NIMG;
    const float* __restrict__ lg = logits + (size_t)img * IMG;
    const int*   __restrict__ tg = target + (size_t)img * IMG;
    const __half* __restrict__ sp = (MODE != 0) ? src + (size_t)z * IMG : nullptr;
    __half* __restrict__ dp = (MODE != 2) ? dst + (size_t)z * IMG : nullptr;

    const __half2 INF2  = __half2half2(__ushort_as_half(0x7C00));
    const __half2 NINF2 = __half2half2(__ushort_as_half(0xFC00));
    h8 P8; P8.a = INF2;  P8.b = INF2;  P8.c = INF2;  P8.d = INF2;
    h8 N8; N8.a = NINF2; N8.b = NINF2; N8.c = NINF2; N8.d = NINF2;
    const __half2 mN2 = colsOK ? INF2 : NINF2;   // apply with hmin2
    const __half2 mP2 = colsOK ? NINF2 : INF2;   // apply with hmax2

    const bool emitLane = (lane >= 1) && (lane <= 30) && colsOK;

    auto ldF = [&](int r) -> h8 {               // no checks (interior)
        size_t off = (size_t)r * IMG_W + c0;
        if (MODE == 0) {
            h8 o;
            if (z < NIMG) {
                float4 f1 = __ldg((const float4*)(lg + off));
                float4 f2 = __ldg((const float4*)(lg + off + 4));
                o.a = __floats2half2_rn(sigmoidf(f1.x), sigmoidf(f1.y));
                o.b = __floats2half2_rn(sigmoidf(f1.z), sigmoidf(f1.w));
                o.c = __floats2half2_rn(sigmoidf(f2.x), sigmoidf(f2.y));
                o.d = __floats2half2_rn(sigmoidf(f2.z), sigmoidf(f2.w));
            } else {
                int4 t1 = __ldg((const int4*)(tg + off));
                int4 t2 = __ldg((const int4*)(tg + off + 4));
                o.a = __floats2half2_rn((float)t1.x, (float)t1.y);
                o.b = __floats2half2_rn((float)t1.z, (float)t1.w);
                o.c = __floats2half2_rn((float)t2.x, (float)t2.y);
                o.d = __floats2half2_rn((float)t2.z, (float)t2.w);
            }
            return o;
        }
        uint4 u = __ldg((const uint4*)(sp + off));
        h8 o; o.a = u2h(u.x); o.b = u2h(u.y); o.c = u2h(u.z); o.d = u2h(u.w);
        return o;
    };
    auto ldrow = [&](int r) -> h8 {             // checked (edges)
        if (!colsOK || (unsigned)r >= IMG_H) return P8;
        return ldF(r);
    };
    auto store8 = [&](int r, h8 v) {
        uint4 u; u.x = h2u(v.a); u.y = h2u(v.b); u.z = h2u(v.c); u.w = h2u(v.d);
        *(uint4*)(dp + (size_t)r * IMG_W + c0) = u;
    };

    const bool cint = (blockIdx.x > 0) && (blockIdx.x < gridDim.x - 1);
    const bool rint = (row0 >= 4) && (row0 + R + 4 <= IMG_H);
    float accum = 0.f;

    if (MODE != 2) {
        if (cint && rint) {
            // ---- FAST: two fused iterations, no checks ----
            h8 xa = ldF(row0 - 4), xb = ldF(row0 - 3);
            h8 e1a = N8, e1b = N8, pa = P8, pb = P8, qa = N8, qb = N8;
            #pragma unroll 2
            for (int k = row0 - 3; k <= row0 + R + 2; ++k) {
                h8 xc  = ldF(k + 1);
                h8 e1  = hmin8(vmin38(xa, xb, xc));
                h8 op1 = hmax8(vmax38(e1a, e1b, e1));
                h8 xp  = upd8(xa, op1, e1b);
                h8 e2  = hmin8(vmin38(pa, pb, xp));
                if (k >= row0 + 3) {
                    h8 op2 = hmax8(vmax38(qa, qb, e2));
                    h8 nx  = upd8(pa, op2, qb);
                    if (emitLane) store8(k - 3, nx);
                }
                qa = qb; qb = e2; pa = pb; pb = xp;
                e1a = e1b; e1b = e1; xa = xb; xb = xc;
            }
        } else {
            // ---- CHECKED: row selects + lane-uniform column masks ----
            h8 xa = ldrow(row0 - 4), xb = ldrow(row0 - 3);
            h8 e1a = N8, e1b = N8, pa = P8, pb = P8, qa = N8, qb = N8;
            for (int k = row0 - 3; k <= row0 + R + 2; ++k) {
                h8 xc = ldrow(k + 1);
                h8 e1 = ((unsigned)k < IMG_H)
                      ? maskN8(hmin8(vmin38(xa, xb, xc)), mN2) : N8;
                h8 op1 = hmax8(vmax38(e1a, e1b, e1));
                h8 xp  = ((unsigned)(k - 1) < IMG_H)
                       ? maskP8(upd8(xa, op1, e1b), mP2) : P8;
                h8 e2 = ((unsigned)(k - 2) < IMG_H)
                      ? maskN8(hmin8(vmin38(pa, pb, xp)), mN2) : N8;
                if (k >= row0 + 3) {
                    h8 op2 = hmax8(vmax38(qa, qb, e2));
                    h8 nx  = upd8(pa, op2, qb);
                    if (emitLane) store8(k - 3, nx);
                }
                qa = qb; qb = e2; pa = pb; pb = xp;
                e1a = e1b; e1b = e1; xa = xb; xb = xc;
            }
        }
    } else {
        // ---- final iteration + reduction ----
        auto weight8 = [&](size_t ob, float* w) {
            if (z < NIMG) {
                int4 t1 = __ldg((const int4*)(tg + ob));
                int4 t2 = __ldg((const int4*)(tg + ob + 4));
                w[0]=(float)t1.x; w[1]=(float)t1.y; w[2]=(float)t1.z; w[3]=(float)t1.w;
                w[4]=(float)t2.x; w[5]=(float)t2.y; w[6]=(float)t2.z; w[7]=(float)t2.w;
            } else {
                float4 f1 = __ldg((const float4*)(lg + ob));
                float4 f2 = __ldg((const float4*)(lg + ob + 4));
                w[0]=sigmoidf(f1.x); w[1]=sigmoidf(f1.y); w[2]=sigmoidf(f1.z); w[3]=sigmoidf(f1.w);
                w[4]=sigmoidf(f2.x); w[5]=sigmoidf(f2.y); w[6]=sigmoidf(f2.z); w[7]=sigmoidf(f2.w);
            }
        };
        auto accum8 = [&](int r, h8 nx) {
            size_t ob = (size_t)r * IMG_W + c0;
            float w[8]; weight8(ob, w);
            float2 f0 = __half22float2(nx.a), f1 = __half22float2(nx.b);
            float2 f2 = __half22float2(nx.c), f3 = __half22float2(nx.d);
            accum += f0.x * w[0] + f0.y * w[1] + f1.x * w[2] + f1.y * w[3]
                   + f2.x * w[4] + f2.y * w[5] + f3.x * w[6] + f3.y * w[7];
        };
        if (cint && rint) {
            h8 xa = ldF(row0 - 2), xb = ldF(row0 - 1);
            h8 e1a = N8, e1b = N8;
            #pragma unroll 2
            for (int k = row0 - 1; k <= row0 + R; ++k) {
                h8 xc = ldF(k + 1);
                h8 e1 = hmin8(vmin38(xa, xb, xc));
                if (k >= row0 + 1) {
                    h8 op = hmax8(vmax38(e1a, e1b, e1));
                    h8 nx = upd8(xa, op, e1b);
                    if (emitLane) accum8(k - 1, nx);
                }
                e1a = e1b; e1b = e1; xa = xb; xb = xc;
            }
        } else {
            h8 xa = ldrow(row0 - 2), xb = ldrow(row0 - 1);
            h8 e1a = N8, e1b = N8;
            for (int k = row0 - 1; k <= row0 + R; ++k) {
                h8 xc = ldrow(k + 1);
                h8 e1 = ((unsigned)k < IMG_H)
                      ? maskN8(hmin8(vmin38(xa, xb, xc)), mN2) : N8;
                if (k >= row0 + 1) {
                    h8 op = hmax8(vmax38(e1a, e1b, e1));
                    h8 nx = upd8(xa, op, e1b);
                    if (emitLane) accum8(k - 1, nx);
                }
                e1a = e1b; e1b = e1; xa = xb; xb = xc;
            }
        }
        #pragma unroll
        for (int o = 16; o > 0; o >>= 1)
            accum += __shfl_down_sync(0xffffffffu, accum, o);
        __shared__ float sacc[NWARP];
        if (lane == 0) sacc[warp] = accum;
        __syncthreads();
        if (threadIdx.x == 0) {
            float t = 0.f;
            #pragma unroll
            for (int i = 0; i < NWARP; ++i) t += sacc[i];
            atomicAdd(&g_acc[z], (double)t);
        }
    }
}

// ---------------------------------------------------------------------------
__global__ void final_kernel(float* __restrict__ out)
{
    const int t = threadIdx.x;
    float v = 0.f;
    if (t < NIMG) {
        double tp = g_acc[t], ts = g_acc[NIMG + t];
        double num = 2.0 * tp * ts;
        double den = tp + ts;
        double c = (den > 0.0) ? (num + 1e-6) / (den + 1e-6) : 1.0;
        c = fmin(fmax(c, 0.0), 1.0);
        v = (float)(1.0 - c);
    }
    for (int o = 16; o > 0; o >>= 1) v += __shfl_down_sync(0xffffffffu, v, o);
    if (t == 0) out[0] = v / (float)NIMG;
}

// ---------------------------------------------------------------------------
extern "C" void kernel_launch(void* const* d_in, const int* in_sizes, int n_in,
                              void* d_out, int out_size)
{
    const float* logits = (const float*)d_in[0];
    const int*   target = (const int*)d_in[1];
    float*       out    = (float*)d_out;

    __half *A = nullptr, *B = nullptr;
    cudaGetSymbolAddress((void**)&A, g_bufA);
    cudaGetSymbolAddress((void**)&B, g_bufB);

    dim3 grid(XT, IMG_H / (R * NWARP), NF);   // 5 x 8 x 32 = 1280 blocks
    const int blk = NWARP * 32;

    skel_kernel<0><<<grid, blk>>>(nullptr, logits, target, A);  // sigmoid + iters 1-2
    skel_kernel<1><<<grid, blk>>>(A, nullptr, nullptr, B);      // iters 3-4
    skel_kernel<2><<<grid, blk>>>(B, logits, target, nullptr);  // iter 5 + reduce
    final_kernel<<<1, 32>>>(out);
}